// round 1
// baseline (speedup 1.0000x reference)
#include <cuda_runtime.h>
#include <cuda_bf16.h>
#include <math.h>

// Shapes (fixed for this problem)
#define NB    4
#define NQ    300
#define NROW  1200     // NB*NQ
#define NWL   8
#define NH    64
#define NW    64
#define ND    256
#define NM    4

// Scratch (device globals — no allocation allowed)
__device__ float g_AGG[NROW * ND];        // aggregated sampled features
__device__ float g_H  [NROW * ND];        // ln2(out)
__device__ float g_G  [NROW * 4 * ND];    // gelu(H @ w_ffn1 + b1)
__device__ float g_Wc [64 * 16];          // w_rel @ [w_delta_bot | w_alpha_bot]
__device__ float g_bc [16];               // combined bias

// ---------------------------------------------------------------------------
// block-wide sum over 256 threads (deterministic)
__device__ __forceinline__ float blockReduce256(float v, float* sred) {
#pragma unroll
    for (int o = 16; o > 0; o >>= 1) v += __shfl_xor_sync(0xffffffffu, v, o);
    int lane = threadIdx.x & 31, w = threadIdx.x >> 5;
    __syncthreads();               // protect sred reuse across calls
    if (lane == 0) sred[w] = v;
    __syncthreads();
    return sred[0] + sred[1] + sred[2] + sred[3] + sred[4] + sred[5] + sred[6] + sred[7];
}

// ---------------------------------------------------------------------------
// Precompute Wcomb[p][j] = sum_k w_rel[p,k] * Wbot[k][j]  (p<64) and
// bcomb[j] = b_delta/b_alpha[j] + sum_k b_rel[k] * Wbot[k][j]  (block 64)
__global__ void __launch_bounds__(256) precomp_kernel(
    const float* __restrict__ w_rel, const float* __restrict__ b_rel,
    const float* __restrict__ w_delta, const float* __restrict__ b_delta,
    const float* __restrict__ w_alpha, const float* __restrict__ b_alpha,
    float* __restrict__ Wc, float* __restrict__ bc)
{
    __shared__ float sp[256][17];
    int p = blockIdx.x;            // 0..63 -> Wcomb row, 64 -> bias row
    int tid = threadIdx.x;
    float a = (p < 64) ? w_rel[p * 256 + tid] : b_rel[tid];
#pragma unroll
    for (int j = 0; j < 12; j++) sp[tid][j] = a * w_delta[(256 + tid) * 12 + j];
#pragma unroll
    for (int j = 0; j < 4; j++)  sp[tid][12 + j] = a * w_alpha[(256 + tid) * 4 + j];
    __syncthreads();
    for (int s = 128; s > 0; s >>= 1) {
        if (tid < s) {
#pragma unroll
            for (int j = 0; j < 16; j++) sp[tid][j] += sp[tid + s][j];
        }
        __syncthreads();
    }
    if (tid < 16) {
        if (p < 64) Wc[p * 16 + tid] = sp[0][tid];
        else        bc[tid] = sp[0][tid] + ((tid < 12) ? b_delta[tid] : b_alpha[tid - 12]);
    }
}

// ---------------------------------------------------------------------------
// Main deformable-sampling kernel: one CTA per (b,q) row, 256 threads (one per D)
__global__ void __launch_bounds__(256) deform_kernel(
    const float* __restrict__ q, const float* __restrict__ feats,
    const unsigned char* __restrict__ kmask, const float* __restrict__ ds,
    const float* __restrict__ w_ref, const float* __restrict__ b_ref,
    const float* __restrict__ w_delta, const float* __restrict__ w_alpha,
    const float* __restrict__ lam,
    const float* __restrict__ ln1g, const float* __restrict__ ln1b,
    const float* __restrict__ Wc, const float* __restrict__ bc,
    float* __restrict__ AGG)
{
    int row = blockIdx.x;                 // 0..1199
    int b   = row / NQ;
    int tid = threadIdx.x;

    __shared__ float s_red[8];
    __shared__ float s_ref[2];
    __shared__ float s_ds[NWL];
    __shared__ float s_pe[NWL][64];
    __shared__ float s_Wc[64][17];
    __shared__ float s_top[16];
    __shared__ float s_dl[NWL][16];
    __shared__ float s_wt[NWL][NM];
    __shared__ float s_tan[NWL][12];
    __shared__ float s_samp[32][10];
    __shared__ float s_part[256][17];

    // ---- LN1 ----
    float qv   = q[row * ND + tid];
    float mean = blockReduce256(qv, s_red) * (1.f / 256.f);
    float dd   = qv - mean;
    float var  = blockReduce256(dd * dd, s_red) * (1.f / 256.f);
    float qn   = dd * rsqrtf(var + 1e-5f) * ln1g[tid] + ln1b[tid];

    // ---- reference point: sigmoid(qn @ w_ref + b_ref) ----
    float r0 = blockReduce256(qn * w_ref[2 * tid + 0], s_red);
    float r1 = blockReduce256(qn * w_ref[2 * tid + 1], s_red);
    if (tid == 0) {
        s_ref[0] = 1.f / (1.f + expf(-(r0 + b_ref[0])));
        s_ref[1] = 1.f / (1.f + expf(-(r1 + b_ref[1])));
    }
    if (tid < NWL) s_ds[tid] = ds[row * NWL + tid];

    // stage Wcomb to smem (padded: conflict-free)
    for (int e = tid; e < 64 * 16; e += 256) s_Wc[e >> 4][e & 15] = Wc[e];

    // sinusoidal PE for all 8 windows (512 values, 2 per thread)
    for (int e = tid; e < NWL * 64; e += 256) {
        int w = e >> 6, p = e & 63;
        float t = ds[row * NWL + w];
        float v;
        if (p < 32) v = sinf(t * expf(-0.28782313662425575f * (float)p));
        else        v = cosf(t * expf(-0.28782313662425575f * (float)(p - 32)));
        s_pe[w][p] = v;
    }

    // ---- top[j] = qn @ Wtop[:,j] partials, tree-reduced ----
#pragma unroll
    for (int j = 0; j < 12; j++) s_part[tid][j]      = qn * w_delta[tid * 12 + j];
#pragma unroll
    for (int j = 0; j < 4;  j++) s_part[tid][12 + j] = qn * w_alpha[tid * 4 + j];
    __syncthreads();
    for (int s = 128; s > 0; s >>= 1) {
        if (tid < s) {
#pragma unroll
            for (int j = 0; j < 16; j++) s_part[tid][j] += s_part[tid + s][j];
        }
        __syncthreads();
    }
    if (tid < 16) s_top[tid] = s_part[0][tid];
    __syncthreads();

    // ---- per-window delta/logits: dl[w][j] = top[j] + pe_w @ Wc[:,j] + bc[j] ----
    if (tid < 128) {
        int w = tid >> 4, j = tid & 15;
        float acc = s_top[j] + bc[j];
#pragma unroll
        for (int p = 0; p < 64; p++) acc = fmaf(s_pe[w][p], s_Wc[p][j], acc);
        s_dl[w][j] = acc;
    }
    __syncthreads();

    // ---- softmax weights (threads 0..7) + tanh precompute (threads 32..127) ----
    if (tid < NWL) {
        float sp  = log1pf(expf(lam[0]));
        float pen = sp * fabsf(s_ds[tid]);
        float z0 = s_dl[tid][12] - pen, z1 = s_dl[tid][13] - pen;
        float z2 = s_dl[tid][14] - pen, z3 = s_dl[tid][15] - pen;
        float mx = fmaxf(fmaxf(z0, z1), fmaxf(z2, z3));
        float e0 = expf(z0 - mx), e1 = expf(z1 - mx), e2 = expf(z2 - mx), e3 = expf(z3 - mx);
        float inv = 1.f / (e0 + e1 + e2 + e3);
        s_wt[tid][0] = e0 * inv; s_wt[tid][1] = e1 * inv;
        s_wt[tid][2] = e2 * inv; s_wt[tid][3] = e3 * inv;
    }
    if (tid >= 32 && tid < 128) {
        int t2 = tid - 32;
        int w = t2 / 12, j = t2 % 12;
        s_tan[w][j] = tanhf(s_dl[w][j]);
    }
    __syncthreads();

    // ---- per-(w,m) sampling parameters (threads 0..31) ----
    if (tid < 32) {
        int w = tid >> 2, m = tid & 3;
        float cx = fminf(fmaxf(s_ref[0] + s_tan[w][m * 3 + 0], 0.f), 1.f);
        float cy = fminf(fmaxf(s_ref[1] + s_tan[w][m * 3 + 1], 0.f), 1.f);
        float dt = s_tan[w][m * 3 + 2];
        float target = (float)w + dt;
        float t0f = fminf(fmaxf(floorf(target), 0.f), (float)(NWL - 1));
        float t1f = fminf(t0f + 1.f, (float)(NWL - 1));
        float alpha = target - t0f;
        float px = cx * (float)NW - 0.5f, py = cy * (float)NH - 0.5f;
        float x0f = floorf(px), y0f = floorf(py);
        s_samp[tid][0] = __int_as_float(min(max((int)x0f, 0), NW - 1));
        s_samp[tid][1] = __int_as_float(min(max((int)x0f + 1, 0), NW - 1));
        s_samp[tid][2] = px - x0f;
        s_samp[tid][3] = __int_as_float(min(max((int)y0f, 0), NH - 1));
        s_samp[tid][4] = __int_as_float(min(max((int)y0f + 1, 0), NH - 1));
        s_samp[tid][5] = py - y0f;
        s_samp[tid][6] = __int_as_float((int)t0f);
        s_samp[tid][7] = __int_as_float((int)t1f);
        s_samp[tid][8] = alpha;
        s_samp[tid][9] = s_wt[w][m];
    }
    __syncthreads();

    // ---- gather + aggregate (all 256 threads, one channel each) ----
    float agg = 0.f;
    for (int s = 0; s < 32; s++) {
        int   x0 = __float_as_int(s_samp[s][0]);
        int   x1 = __float_as_int(s_samp[s][1]);
        float wx = s_samp[s][2];
        int   y0 = __float_as_int(s_samp[s][3]);
        int   y1 = __float_as_int(s_samp[s][4]);
        float wy = s_samp[s][5];
        int   t0 = __float_as_int(s_samp[s][6]);
        int   t1 = __float_as_int(s_samp[s][7]);
        float alpha = s_samp[s][8];
        float wgt   = s_samp[s][9];

        float sv0, sv1;
        {
            int pb  = ((b * NWL + t0) * NH) * NW;
            int c00 = pb + y0 * NW + x0, c01 = pb + y0 * NW + x1;
            int c10 = pb + y1 * NW + x0, c11 = pb + y1 * NW + x1;
            float f00 = kmask[c00] ? 0.f : feats[c00 * ND + tid];
            float f01 = kmask[c01] ? 0.f : feats[c01 * ND + tid];
            float f10 = kmask[c10] ? 0.f : feats[c10 * ND + tid];
            float f11 = kmask[c11] ? 0.f : feats[c11 * ND + tid];
            sv0 = (f00 * (1.f - wx) + f01 * wx) * (1.f - wy)
                + (f10 * (1.f - wx) + f11 * wx) * wy;
        }
        {
            int pb  = ((b * NWL + t1) * NH) * NW;
            int c00 = pb + y0 * NW + x0, c01 = pb + y0 * NW + x1;
            int c10 = pb + y1 * NW + x0, c11 = pb + y1 * NW + x1;
            float f00 = kmask[c00] ? 0.f : feats[c00 * ND + tid];
            float f01 = kmask[c01] ? 0.f : feats[c01 * ND + tid];
            float f10 = kmask[c10] ? 0.f : feats[c10 * ND + tid];
            float f11 = kmask[c11] ? 0.f : feats[c11 * ND + tid];
            sv1 = (f00 * (1.f - wx) + f01 * wx) * (1.f - wy)
                + (f10 * (1.f - wx) + f11 * wx) * wy;
        }
        agg += wgt * (sv0 * (1.f - alpha) + sv1 * alpha);
    }
    AGG[row * ND + tid] = agg;
}

// ---------------------------------------------------------------------------
// LN2: H = layernorm(out) * g + b
__global__ void __launch_bounds__(256) ln2_kernel(
    const float* __restrict__ out, const float* __restrict__ g,
    const float* __restrict__ bpar, float* __restrict__ Hbuf)
{
    __shared__ float s_red[8];
    int row = blockIdx.x, tid = threadIdx.x;
    float v    = out[row * ND + tid];
    float mean = blockReduce256(v, s_red) * (1.f / 256.f);
    float d    = v - mean;
    float var  = blockReduce256(d * d, s_red) * (1.f / 256.f);
    Hbuf[row * ND + tid] = d * rsqrtf(var + 1e-5f) * g[tid] + bpar[tid];
}

// ---------------------------------------------------------------------------
// Tiled fp32 GEMM:  C[, ] (=|+=) epilogue( A[M,K] @ W[K,N] + bias (+ resid) )
template<int BM, int BN, int BK, int TM, int TN, bool GELU, bool ACC, bool RESID>
__global__ void __launch_bounds__(256) gemm_k(
    const float* __restrict__ A, const float* __restrict__ W,
    const float* __restrict__ bias, const float* __restrict__ resid,
    float* __restrict__ C, int M, int N, int K)
{
    __shared__ float As[BM][BK + 1];
    __shared__ float Bs[BK][BN];
    const int TX = BN / TN;
    int tid = threadIdx.x;
    int tx = tid % TX, ty = tid / TX;
    int m0 = blockIdx.x * BM, n0 = blockIdx.y * BN;
    float acc[TM][TN];
#pragma unroll
    for (int i = 0; i < TM; i++)
#pragma unroll
        for (int j = 0; j < TN; j++) acc[i][j] = 0.f;

    for (int k0 = 0; k0 < K; k0 += BK) {
#pragma unroll
        for (int e = tid; e < BM * BK; e += 256) {
            int m = e / BK, k = e % BK;
            int gm = m0 + m;
            As[m][k] = (gm < M) ? A[gm * K + k0 + k] : 0.f;
        }
#pragma unroll
        for (int e = tid; e < BK * BN; e += 256) {
            int k = e / BN, n = e % BN;
            Bs[k][n] = W[(k0 + k) * N + n0 + n];
        }
        __syncthreads();
#pragma unroll
        for (int k = 0; k < BK; k++) {
            float a[TM], bb[TN];
#pragma unroll
            for (int i = 0; i < TM; i++) a[i] = As[ty * TM + i][k];
#pragma unroll
            for (int j = 0; j < TN; j++) bb[j] = Bs[k][tx * TN + j];
#pragma unroll
            for (int i = 0; i < TM; i++)
#pragma unroll
                for (int j = 0; j < TN; j++) acc[i][j] = fmaf(a[i], bb[j], acc[i][j]);
        }
        __syncthreads();
    }
#pragma unroll
    for (int i = 0; i < TM; i++) {
        int gm = m0 + ty * TM + i;
        if (gm >= M) continue;
#pragma unroll
        for (int j = 0; j < TN; j++) {
            int gn = n0 + tx * TN + j;
            float v = acc[i][j] + bias[gn];
            if (RESID) v += resid[gm * N + gn];
            if (GELU)  v = 0.5f * v * (1.f + erff(v * 0.70710678118654752f));
            if (ACC) C[gm * N + gn] += v; else C[gm * N + gn] = v;
        }
    }
}

// ---------------------------------------------------------------------------
extern "C" void kernel_launch(void* const* d_in, const int* in_sizes, int n_in,
                              void* d_out, int out_size)
{
    const float* q       = (const float*)d_in[0];
    const float* feats   = (const float*)d_in[1];
    const unsigned char* kmask = (const unsigned char*)d_in[2];
    const float* ds      = (const float*)d_in[3];
    const float* w_ref   = (const float*)d_in[4];
    const float* b_ref   = (const float*)d_in[5];
    const float* w_delta = (const float*)d_in[6];
    const float* b_delta = (const float*)d_in[7];
    const float* w_alpha = (const float*)d_in[8];
    const float* b_alpha = (const float*)d_in[9];
    const float* lam     = (const float*)d_in[10];
    const float* w_proj  = (const float*)d_in[11];
    const float* b_proj  = (const float*)d_in[12];
    const float* ln1g    = (const float*)d_in[13];
    const float* ln1b    = (const float*)d_in[14];
    const float* ln2g    = (const float*)d_in[15];
    const float* ln2b    = (const float*)d_in[16];
    const float* w_ffn1  = (const float*)d_in[17];
    const float* b_ffn1  = (const float*)d_in[18];
    const float* w_ffn2  = (const float*)d_in[19];
    const float* b_ffn2  = (const float*)d_in[20];
    const float* w_rel   = (const float*)d_in[21];
    const float* b_rel   = (const float*)d_in[22];
    float* out = (float*)d_out;

    float *pAGG, *pH, *pG, *pWc, *pbc;
    cudaGetSymbolAddress((void**)&pAGG, g_AGG);
    cudaGetSymbolAddress((void**)&pH,   g_H);
    cudaGetSymbolAddress((void**)&pG,   g_G);
    cudaGetSymbolAddress((void**)&pWc,  g_Wc);
    cudaGetSymbolAddress((void**)&pbc,  g_bc);

    // 1) fold w_rel into the delta/alpha projections
    precomp_kernel<<<65, 256>>>(w_rel, b_rel, w_delta, b_delta, w_alpha, b_alpha, pWc, pbc);

    // 2) deformable sampling + aggregation -> AGG[1200,256]
    deform_kernel<<<NROW, 256>>>(q, feats, kmask, ds, w_ref, b_ref,
                                 w_delta, w_alpha, lam, ln1g, ln1b, pWc, pbc, pAGG);

    // 3) out = q + AGG @ w_proj + b_proj      (M=1200,N=256,K=256)
    gemm_k<32, 64, 32, 2, 4, false, false, true>
        <<<dim3((NROW + 31) / 32, ND / 64), 256>>>(pAGG, w_proj, b_proj, q, out, NROW, ND, ND);

    // 4) H = LN2(out)
    ln2_kernel<<<NROW, 256>>>(out, ln2g, ln2b, pH);

    // 5) G = gelu(H @ w_ffn1 + b_ffn1)        (M=1200,N=1024,K=256)
    gemm_k<64, 64, 32, 4, 4, true, false, false>
        <<<dim3((NROW + 63) / 64, (4 * ND) / 64), 256>>>(pH, w_ffn1, b_ffn1, nullptr, pG, NROW, 4 * ND, ND);

    // 6) out += G @ w_ffn2 + b_ffn2           (M=1200,N=256,K=1024)
    gemm_k<32, 64, 32, 2, 4, false, true, false>
        <<<dim3((NROW + 31) / 32, ND / 64), 256>>>(pG, w_ffn2, b_ffn2, nullptr, out, NROW, ND, 4 * ND);
}

// round 2
// speedup vs baseline: 1.2961x; 1.2961x over previous
#include <cuda_runtime.h>
#include <cuda_bf16.h>
#include <math.h>

// Shapes (fixed for this problem)
#define NB    4
#define NQ    300
#define NROW  1200     // NB*NQ
#define NWL   8
#define NH    64
#define NW    64
#define ND    256
#define NM    4

// Scratch (device globals — no allocation allowed)
__device__ float  g_AGG[NROW * ND];        // aggregated sampled features
__device__ float  g_H  [NROW * ND];        // ln2(out)
__device__ float  g_G  [NROW * 4 * ND];    // gelu(H @ w_ffn1 + b1)
__device__ float  g_Wc [64 * 16];          // w_rel @ [w_delta_bot | w_alpha_bot]
__device__ float  g_bc [16];               // combined bias
__device__ float2 g_PAIR[NROW * 256];      // (cell offset as int bits, weight)

// ---------------------------------------------------------------------------
// block-wide sum over 256 threads (deterministic)
__device__ __forceinline__ float blockReduce256(float v, float* sred) {
#pragma unroll
    for (int o = 16; o > 0; o >>= 1) v += __shfl_xor_sync(0xffffffffu, v, o);
    int lane = threadIdx.x & 31, w = threadIdx.x >> 5;
    __syncthreads();               // protect sred reuse across calls
    if (lane == 0) sred[w] = v;
    __syncthreads();
    return sred[0] + sred[1] + sred[2] + sred[3] + sred[4] + sred[5] + sred[6] + sred[7];
}

// ---------------------------------------------------------------------------
// Precompute Wcomb[p][j] = sum_k w_rel[p,k] * Wbot[k][j]  (p<64) and
// bcomb[j] = b_delta/b_alpha[j] + sum_k b_rel[k] * Wbot[k][j]  (block 64)
__global__ void __launch_bounds__(256) precomp_kernel(
    const float* __restrict__ w_rel, const float* __restrict__ b_rel,
    const float* __restrict__ w_delta, const float* __restrict__ b_delta,
    const float* __restrict__ w_alpha, const float* __restrict__ b_alpha,
    float* __restrict__ Wc, float* __restrict__ bc)
{
    __shared__ float sp[256][17];
    int p = blockIdx.x;            // 0..63 -> Wcomb row, 64 -> bias row
    int tid = threadIdx.x;
    float a = (p < 64) ? w_rel[p * 256 + tid] : b_rel[tid];
#pragma unroll
    for (int j = 0; j < 12; j++) sp[tid][j] = a * w_delta[(256 + tid) * 12 + j];
#pragma unroll
    for (int j = 0; j < 4; j++)  sp[tid][12 + j] = a * w_alpha[(256 + tid) * 4 + j];
    __syncthreads();
    for (int s = 128; s > 0; s >>= 1) {
        if (tid < s) {
#pragma unroll
            for (int j = 0; j < 16; j++) sp[tid][j] += sp[tid + s][j];
        }
        __syncthreads();
    }
    if (tid < 16) {
        if (p < 64) Wc[p * 16 + tid] = sp[0][tid];
        else        bc[tid] = sp[0][tid] + ((tid < 12) ? b_delta[tid] : b_alpha[tid - 12]);
    }
}

// ---------------------------------------------------------------------------
// Parameter kernel: one CTA per (b,q) row. Produces 256 (offset, weight)
// pairs per query: 32 samples x 8 trilinear corners, with mask/softmax/
// bilinear/temporal weights all folded into one scalar weight.
__global__ void __launch_bounds__(256) param_kernel(
    const float* __restrict__ q,
    const unsigned char* __restrict__ kmask, const float* __restrict__ ds,
    const float* __restrict__ w_ref, const float* __restrict__ b_ref,
    const float* __restrict__ w_delta, const float* __restrict__ w_alpha,
    const float* __restrict__ lam,
    const float* __restrict__ ln1g, const float* __restrict__ ln1b,
    const float* __restrict__ Wc, const float* __restrict__ bc,
    float2* __restrict__ PAIR)
{
    int row = blockIdx.x;                 // 0..1199
    int b   = row / NQ;
    int tid = threadIdx.x;

    __shared__ float s_red[8];
    __shared__ float s_ref[2];
    __shared__ float s_ds[NWL];
    __shared__ float s_pe[NWL][64];
    __shared__ float s_Wc[64][17];
    __shared__ float s_top[16];
    __shared__ float s_dl[NWL][16];
    __shared__ float s_wt[NWL][NM];
    __shared__ float s_tan[NWL][12];
    __shared__ float s_samp[32][10];
    __shared__ float s_part[256][17];

    // ---- LN1 ----
    float qv   = q[row * ND + tid];
    float mean = blockReduce256(qv, s_red) * (1.f / 256.f);
    float dd   = qv - mean;
    float var  = blockReduce256(dd * dd, s_red) * (1.f / 256.f);
    float qn   = dd * rsqrtf(var + 1e-5f) * ln1g[tid] + ln1b[tid];

    // ---- reference point: sigmoid(qn @ w_ref + b_ref) ----
    float r0 = blockReduce256(qn * w_ref[2 * tid + 0], s_red);
    float r1 = blockReduce256(qn * w_ref[2 * tid + 1], s_red);
    if (tid == 0) {
        s_ref[0] = 1.f / (1.f + expf(-(r0 + b_ref[0])));
        s_ref[1] = 1.f / (1.f + expf(-(r1 + b_ref[1])));
    }
    if (tid < NWL) s_ds[tid] = ds[row * NWL + tid];

    // stage Wcomb to smem (padded: conflict-free)
    for (int e = tid; e < 64 * 16; e += 256) s_Wc[e >> 4][e & 15] = Wc[e];

    // sinusoidal PE for all 8 windows (512 values, 2 per thread)
    for (int e = tid; e < NWL * 64; e += 256) {
        int w = e >> 6, p = e & 63;
        float t = ds[row * NWL + w];
        float v;
        if (p < 32) v = sinf(t * expf(-0.28782313662425575f * (float)p));
        else        v = cosf(t * expf(-0.28782313662425575f * (float)(p - 32)));
        s_pe[w][p] = v;
    }

    // ---- top[j] = qn @ Wtop[:,j] partials, tree-reduced ----
#pragma unroll
    for (int j = 0; j < 12; j++) s_part[tid][j]      = qn * w_delta[tid * 12 + j];
#pragma unroll
    for (int j = 0; j < 4;  j++) s_part[tid][12 + j] = qn * w_alpha[tid * 4 + j];
    __syncthreads();
    for (int s = 128; s > 0; s >>= 1) {
        if (tid < s) {
#pragma unroll
            for (int j = 0; j < 16; j++) s_part[tid][j] += s_part[tid + s][j];
        }
        __syncthreads();
    }
    if (tid < 16) s_top[tid] = s_part[0][tid];
    __syncthreads();

    // ---- per-window delta/logits: dl[w][j] = top[j] + pe_w @ Wc[:,j] + bc[j] ----
    if (tid < 128) {
        int w = tid >> 4, j = tid & 15;
        float acc = s_top[j] + bc[j];
#pragma unroll
        for (int p = 0; p < 64; p++) acc = fmaf(s_pe[w][p], s_Wc[p][j], acc);
        s_dl[w][j] = acc;
    }
    __syncthreads();

    // ---- softmax weights (threads 0..7) + tanh precompute (threads 32..127) ----
    if (tid < NWL) {
        float sp  = log1pf(expf(lam[0]));
        float pen = sp * fabsf(s_ds[tid]);
        float z0 = s_dl[tid][12] - pen, z1 = s_dl[tid][13] - pen;
        float z2 = s_dl[tid][14] - pen, z3 = s_dl[tid][15] - pen;
        float mx = fmaxf(fmaxf(z0, z1), fmaxf(z2, z3));
        float e0 = expf(z0 - mx), e1 = expf(z1 - mx), e2 = expf(z2 - mx), e3 = expf(z3 - mx);
        float inv = 1.f / (e0 + e1 + e2 + e3);
        s_wt[tid][0] = e0 * inv; s_wt[tid][1] = e1 * inv;
        s_wt[tid][2] = e2 * inv; s_wt[tid][3] = e3 * inv;
    }
    if (tid >= 32 && tid < 128) {
        int t2 = tid - 32;
        int w = t2 / 12, j = t2 % 12;
        s_tan[w][j] = tanhf(s_dl[w][j]);
    }
    __syncthreads();

    // ---- per-(w,m) sampling parameters (threads 0..31) ----
    if (tid < 32) {
        int w = tid >> 2, m = tid & 3;
        float cx = fminf(fmaxf(s_ref[0] + s_tan[w][m * 3 + 0], 0.f), 1.f);
        float cy = fminf(fmaxf(s_ref[1] + s_tan[w][m * 3 + 1], 0.f), 1.f);
        float dt = s_tan[w][m * 3 + 2];
        float target = (float)w + dt;
        float t0f = fminf(fmaxf(floorf(target), 0.f), (float)(NWL - 1));
        float t1f = fminf(t0f + 1.f, (float)(NWL - 1));
        float alpha = target - t0f;
        float px = cx * (float)NW - 0.5f, py = cy * (float)NH - 0.5f;
        float x0f = floorf(px), y0f = floorf(py);
        s_samp[tid][0] = __int_as_float(min(max((int)x0f, 0), NW - 1));
        s_samp[tid][1] = __int_as_float(min(max((int)x0f + 1, 0), NW - 1));
        s_samp[tid][2] = px - x0f;
        s_samp[tid][3] = __int_as_float(min(max((int)y0f, 0), NH - 1));
        s_samp[tid][4] = __int_as_float(min(max((int)y0f + 1, 0), NH - 1));
        s_samp[tid][5] = py - y0f;
        s_samp[tid][6] = __int_as_float((int)t0f);
        s_samp[tid][7] = __int_as_float((int)t1f);
        s_samp[tid][8] = alpha;
        s_samp[tid][9] = s_wt[w][m];
    }
    __syncthreads();

    // ---- emit 256 (offset, weight) pairs: sample s = tid>>3, corner c = tid&7
    {
        int s = tid >> 3, c = tid & 7;
        int   x  = __float_as_int(s_samp[s][(c & 1) ? 1 : 0]);
        float wxv = s_samp[s][2];
        float wxc = (c & 1) ? wxv : (1.f - wxv);
        int   y  = __float_as_int(s_samp[s][(c & 2) ? 4 : 3]);
        float wyv = s_samp[s][5];
        float wyc = (c & 2) ? wyv : (1.f - wyv);
        int   t  = __float_as_int(s_samp[s][(c & 4) ? 7 : 6]);
        float al = s_samp[s][8];
        float twc = (c & 4) ? al : (1.f - al);
        float wgt = s_samp[s][9];

        int cell = ((b * NWL + t) * NH + y) * NW + x;
        float wfin = wgt * twc * wyc * wxc;
        if (kmask[cell]) wfin = 0.f;
        PAIR[row * 256 + tid] = make_float2(__int_as_float(cell), wfin);
    }
}

// ---------------------------------------------------------------------------
// Gather kernel: one CTA per query; 256 threads = 64 channel-quads x 4
// pair-groups. Pure float4 weighted row-gathers, then 4-way smem reduction.
__global__ void __launch_bounds__(256) gather_kernel(
    const float4* __restrict__ feats4, const float2* __restrict__ PAIR,
    float4* __restrict__ AGG4)
{
    __shared__ float2 s_pair[256];
    __shared__ float4 s_red[4][64];
    int row = blockIdx.x;
    int tid = threadIdx.x;
    s_pair[tid] = PAIR[row * 256 + tid];
    __syncthreads();

    int cq = tid & 63;    // channel quad (channels 4*cq .. 4*cq+3)
    int g  = tid >> 6;    // pair group 0..3 (64 pairs each)

    float4 acc = make_float4(0.f, 0.f, 0.f, 0.f);
#pragma unroll 4
    for (int i = 0; i < 64; i++) {
        float2 pr = s_pair[g * 64 + i];
        int   off = __float_as_int(pr.x);
        float w   = pr.y;
        float4 v  = feats4[off * 64 + cq];
        acc.x = fmaf(w, v.x, acc.x);
        acc.y = fmaf(w, v.y, acc.y);
        acc.z = fmaf(w, v.z, acc.z);
        acc.w = fmaf(w, v.w, acc.w);
    }
    s_red[g][cq] = acc;
    __syncthreads();
    if (g == 0) {
        float4 a0 = s_red[0][cq], a1 = s_red[1][cq], a2 = s_red[2][cq], a3 = s_red[3][cq];
        float4 t;
        t.x = (a0.x + a1.x) + (a2.x + a3.x);
        t.y = (a0.y + a1.y) + (a2.y + a3.y);
        t.z = (a0.z + a1.z) + (a2.z + a3.z);
        t.w = (a0.w + a1.w) + (a2.w + a3.w);
        AGG4[row * 64 + cq] = t;
    }
}

// ---------------------------------------------------------------------------
// LN2: one warp per row, float4 loads, shuffle-only reduction
__global__ void __launch_bounds__(256) ln2_kernel(
    const float* __restrict__ out, const float* __restrict__ g,
    const float* __restrict__ bpar, float* __restrict__ Hbuf)
{
    int wid = threadIdx.x >> 5, lane = threadIdx.x & 31;
    int row = blockIdx.x * 8 + wid;
    const float4* o4 = (const float4*)out + row * 64;
    float4 v0 = o4[lane * 2], v1 = o4[lane * 2 + 1];
    float s = (v0.x + v0.y) + (v0.z + v0.w) + (v1.x + v1.y) + (v1.z + v1.w);
#pragma unroll
    for (int o = 16; o > 0; o >>= 1) s += __shfl_xor_sync(0xffffffffu, s, o);
    float mean = s * (1.f / 256.f);
    float d0x = v0.x - mean, d0y = v0.y - mean, d0z = v0.z - mean, d0w = v0.w - mean;
    float d1x = v1.x - mean, d1y = v1.y - mean, d1z = v1.z - mean, d1w = v1.w - mean;
    float sq = (d0x*d0x + d0y*d0y) + (d0z*d0z + d0w*d0w)
             + (d1x*d1x + d1y*d1y) + (d1z*d1z + d1w*d1w);
#pragma unroll
    for (int o = 16; o > 0; o >>= 1) sq += __shfl_xor_sync(0xffffffffu, sq, o);
    float inv = rsqrtf(sq * (1.f / 256.f) + 1e-5f);
    const float4* g4 = (const float4*)g;
    const float4* b4 = (const float4*)bpar;
    float4* H4 = (float4*)Hbuf + row * 64;
    float4 ga = g4[lane * 2], gb = g4[lane * 2 + 1];
    float4 ba = b4[lane * 2], bb = b4[lane * 2 + 1];
    float4 r0, r1;
    r0.x = d0x * inv * ga.x + ba.x; r0.y = d0y * inv * ga.y + ba.y;
    r0.z = d0z * inv * ga.z + ba.z; r0.w = d0w * inv * ga.w + ba.w;
    r1.x = d1x * inv * gb.x + bb.x; r1.y = d1y * inv * gb.y + bb.y;
    r1.z = d1z * inv * gb.z + bb.z; r1.w = d1w * inv * gb.w + bb.w;
    H4[lane * 2]     = r0;
    H4[lane * 2 + 1] = r1;
}

// ---------------------------------------------------------------------------
// Tiled fp32 GEMM with float4 global loads:
//   C (=|+=) epilogue( A[M,K] @ W[K,N] + bias (+ resid) )
template<int BM, int BN, int BK, int TM, int TN, bool GELU, bool ACC, bool RESID>
__global__ void __launch_bounds__(256) gemm_k(
    const float* __restrict__ A, const float* __restrict__ W,
    const float* __restrict__ bias, const float* __restrict__ resid,
    float* __restrict__ C, int M, int N, int K)
{
    __shared__ __align__(16) float As[BM][BK + 4];
    __shared__ __align__(16) float Bs[BK][BN + 4];
    const int TX = BN / TN;   // 16
    int tid = threadIdx.x;
    int tx = tid % TX, ty = tid / TX;
    int m0 = blockIdx.x * BM, n0 = blockIdx.y * BN;
    float acc[TM][TN];
#pragma unroll
    for (int i = 0; i < TM; i++)
#pragma unroll
        for (int j = 0; j < TN; j++) acc[i][j] = 0.f;

    for (int k0 = 0; k0 < K; k0 += BK) {
#pragma unroll
        for (int e = tid; e < BM * (BK / 4); e += 256) {
            int m = e / (BK / 4), kq = e % (BK / 4);
            int gm = m0 + m;
            float4 v = make_float4(0.f, 0.f, 0.f, 0.f);
            if (gm < M) v = *(const float4*)(A + gm * K + k0 + kq * 4);
            *(float4*)&As[m][kq * 4] = v;
        }
#pragma unroll
        for (int e = tid; e < BK * (BN / 4); e += 256) {
            int k = e / (BN / 4), nq = e % (BN / 4);
            float4 v = *(const float4*)(W + (k0 + k) * N + n0 + nq * 4);
            *(float4*)&Bs[k][nq * 4] = v;
        }
        __syncthreads();
#pragma unroll
        for (int k = 0; k < BK; k++) {
            float a[TM];
#pragma unroll
            for (int i = 0; i < TM; i++) a[i] = As[ty * TM + i][k];
            float4 bv = *(const float4*)&Bs[k][tx * TN];  // TN == 4
            float bb[4] = {bv.x, bv.y, bv.z, bv.w};
#pragma unroll
            for (int i = 0; i < TM; i++)
#pragma unroll
                for (int j = 0; j < TN; j++) acc[i][j] = fmaf(a[i], bb[j], acc[i][j]);
        }
        __syncthreads();
    }
#pragma unroll
    for (int i = 0; i < TM; i++) {
        int gm = m0 + ty * TM + i;
        if (gm >= M) continue;
#pragma unroll
        for (int j = 0; j < TN; j++) {
            int gn = n0 + tx * TN + j;
            float v = acc[i][j] + bias[gn];
            if (RESID) v += resid[gm * N + gn];
            if (GELU)  v = 0.5f * v * (1.f + erff(v * 0.70710678118654752f));
            if (ACC) C[gm * N + gn] += v; else C[gm * N + gn] = v;
        }
    }
}

// ---------------------------------------------------------------------------
extern "C" void kernel_launch(void* const* d_in, const int* in_sizes, int n_in,
                              void* d_out, int out_size)
{
    const float* q       = (const float*)d_in[0];
    const float* feats   = (const float*)d_in[1];
    const unsigned char* kmask = (const unsigned char*)d_in[2];
    const float* ds      = (const float*)d_in[3];
    const float* w_ref   = (const float*)d_in[4];
    const float* b_ref   = (const float*)d_in[5];
    const float* w_delta = (const float*)d_in[6];
    const float* b_delta = (const float*)d_in[7];
    const float* w_alpha = (const float*)d_in[8];
    const float* b_alpha = (const float*)d_in[9];
    const float* lam     = (const float*)d_in[10];
    const float* w_proj  = (const float*)d_in[11];
    const float* b_proj  = (const float*)d_in[12];
    const float* ln1g    = (const float*)d_in[13];
    const float* ln1b    = (const float*)d_in[14];
    const float* ln2g    = (const float*)d_in[15];
    const float* ln2b    = (const float*)d_in[16];
    const float* w_ffn1  = (const float*)d_in[17];
    const float* b_ffn1  = (const float*)d_in[18];
    const float* w_ffn2  = (const float*)d_in[19];
    const float* b_ffn2  = (const float*)d_in[20];
    const float* w_rel   = (const float*)d_in[21];
    const float* b_rel   = (const float*)d_in[22];
    float* out = (float*)d_out;

    float *pAGG, *pH, *pG, *pWc, *pbc;
    float2* pPAIR;
    cudaGetSymbolAddress((void**)&pAGG,  g_AGG);
    cudaGetSymbolAddress((void**)&pH,    g_H);
    cudaGetSymbolAddress((void**)&pG,    g_G);
    cudaGetSymbolAddress((void**)&pWc,   g_Wc);
    cudaGetSymbolAddress((void**)&pbc,   g_bc);
    cudaGetSymbolAddress((void**)&pPAIR, g_PAIR);

    // 1) fold w_rel into the delta/alpha projections
    precomp_kernel<<<65, 256>>>(w_rel, b_rel, w_delta, b_delta, w_alpha, b_alpha, pWc, pbc);

    // 2) per-query sampling parameters -> 256 (offset, weight) pairs per query
    param_kernel<<<NROW, 256>>>(q, kmask, ds, w_ref, b_ref,
                                w_delta, w_alpha, lam, ln1g, ln1b, pWc, pbc, pPAIR);

    // 3) weighted gather -> AGG[1200,256]
    gather_kernel<<<NROW, 256>>>((const float4*)feats, pPAIR, (float4*)pAGG);

    // 4) out = q + AGG @ w_proj + b_proj      (M=1200,N=256,K=256)
    gemm_k<32, 64, 32, 2, 4, false, false, true>
        <<<dim3((NROW + 31) / 32, ND / 64), 256>>>(pAGG, w_proj, b_proj, q, out, NROW, ND, ND);

    // 5) H = LN2(out)
    ln2_kernel<<<NROW / 8, 256>>>(out, ln2g, ln2b, pH);

    // 6) G = gelu(H @ w_ffn1 + b_ffn1)        (M=1200,N=1024,K=256)
    gemm_k<64, 64, 32, 4, 4, true, false, false>
        <<<dim3((NROW + 63) / 64, (4 * ND) / 64), 256>>>(pH, w_ffn1, b_ffn1, nullptr, pG, NROW, 4 * ND, ND);

    // 7) out += G @ w_ffn2 + b_ffn2           (M=1200,N=256,K=1024)
    gemm_k<32, 64, 32, 2, 4, false, true, false>
        <<<dim3((NROW + 31) / 32, ND / 64), 256>>>(pG, w_ffn2, b_ffn2, nullptr, out, NROW, ND, 4 * ND);
}

// round 4
// speedup vs baseline: 1.6635x; 1.2834x over previous
#include <cuda_runtime.h>
#include <cuda_bf16.h>
#include <math.h>

// Shapes (fixed for this problem)
#define NB    4
#define NQ    300
#define NROW  1200     // NB*NQ
#define NWL   8
#define NH    64
#define NW    64
#define ND    256
#define NM    4

// Scratch (device globals — no allocation allowed)
__device__ float  g_AGG[NROW * ND];        // aggregated sampled features
__device__ float  g_H  [NROW * ND];        // ln2(out)
__device__ float  g_G  [NROW * 4 * ND];    // gelu(H @ w_ffn1 + b1)
__device__ float  g_Wc [64 * 16];          // w_rel @ [w_delta_bot | w_alpha_bot]
__device__ float  g_bc [16];               // combined bias
__device__ float2 g_PAIR[NROW * 256];      // (cell offset as int bits, weight)

// ---------------------------------------------------------------------------
__device__ __forceinline__ unsigned f2tf32(float f) {
    unsigned u;
    asm("cvt.rna.tf32.f32 %0, %1;" : "=r"(u) : "f"(f));
    return u;
}

// block-wide sum over 256 threads (deterministic)
__device__ __forceinline__ float blockReduce256(float v, float* sred) {
#pragma unroll
    for (int o = 16; o > 0; o >>= 1) v += __shfl_xor_sync(0xffffffffu, v, o);
    int lane = threadIdx.x & 31, w = threadIdx.x >> 5;
    __syncthreads();               // protect sred reuse across calls
    if (lane == 0) sred[w] = v;
    __syncthreads();
    return sred[0] + sred[1] + sred[2] + sred[3] + sred[4] + sred[5] + sred[6] + sred[7];
}

// ---------------------------------------------------------------------------
// Precompute Wcomb[p][j] = sum_k w_rel[p,k] * Wbot[k][j]  (p<64) and
// bcomb[j] = b_delta/b_alpha[j] + sum_k b_rel[k] * Wbot[k][j]  (block 64)
__global__ void __launch_bounds__(256) precomp_kernel(
    const float* __restrict__ w_rel, const float* __restrict__ b_rel,
    const float* __restrict__ w_delta, const float* __restrict__ b_delta,
    const float* __restrict__ w_alpha, const float* __restrict__ b_alpha,
    float* __restrict__ Wc, float* __restrict__ bc)
{
    __shared__ float sp[256][17];
    int p = blockIdx.x;            // 0..63 -> Wcomb row, 64 -> bias row
    int tid = threadIdx.x;
    float a = (p < 64) ? w_rel[p * 256 + tid] : b_rel[tid];
#pragma unroll
    for (int j = 0; j < 12; j++) sp[tid][j] = a * w_delta[(256 + tid) * 12 + j];
#pragma unroll
    for (int j = 0; j < 4; j++)  sp[tid][12 + j] = a * w_alpha[(256 + tid) * 4 + j];
    __syncthreads();
    for (int s = 128; s > 0; s >>= 1) {
        if (tid < s) {
#pragma unroll
            for (int j = 0; j < 16; j++) sp[tid][j] += sp[tid + s][j];
        }
        __syncthreads();
    }
    if (tid < 16) {
        if (p < 64) Wc[p * 16 + tid] = sp[0][tid];
        else        bc[tid] = sp[0][tid] + ((tid < 12) ? b_delta[tid] : b_alpha[tid - 12]);
    }
}

// ---------------------------------------------------------------------------
// Parameter kernel: one CTA per (b,q) row. Produces 256 (offset, weight)
// pairs per query: 32 samples x 8 trilinear corners.
__global__ void __launch_bounds__(256) param_kernel(
    const float* __restrict__ q,
    const unsigned char* __restrict__ kmask, const float* __restrict__ ds,
    const float* __restrict__ w_ref, const float* __restrict__ b_ref,
    const float* __restrict__ w_delta, const float* __restrict__ w_alpha,
    const float* __restrict__ lam,
    const float* __restrict__ ln1g, const float* __restrict__ ln1b,
    const float* __restrict__ Wc, const float* __restrict__ bc,
    float2* __restrict__ PAIR)
{
    int row = blockIdx.x;                 // 0..1199
    int b   = row / NQ;
    int tid = threadIdx.x;

    __shared__ float s_red[8];
    __shared__ float s_ref[2];
    __shared__ float s_ds[NWL];
    __shared__ float s_pe[NWL][64];
    __shared__ float s_Wc[64][17];
    __shared__ float s_top[16];
    __shared__ float s_dl[NWL][16];
    __shared__ float s_wt[NWL][NM];
    __shared__ float s_tan[NWL][12];
    __shared__ float s_samp[32][10];
    __shared__ float s_part[256][17];

    // ---- LN1 ----
    float qv   = q[row * ND + tid];
    float mean = blockReduce256(qv, s_red) * (1.f / 256.f);
    float dd   = qv - mean;
    float var  = blockReduce256(dd * dd, s_red) * (1.f / 256.f);
    float qn   = dd * rsqrtf(var + 1e-5f) * ln1g[tid] + ln1b[tid];

    // ---- reference point: sigmoid(qn @ w_ref + b_ref) ----
    float r0 = blockReduce256(qn * w_ref[2 * tid + 0], s_red);
    float r1 = blockReduce256(qn * w_ref[2 * tid + 1], s_red);
    if (tid == 0) {
        s_ref[0] = 1.f / (1.f + expf(-(r0 + b_ref[0])));
        s_ref[1] = 1.f / (1.f + expf(-(r1 + b_ref[1])));
    }
    if (tid < NWL) s_ds[tid] = ds[row * NWL + tid];

    // stage Wcomb to smem (padded: conflict-free)
    for (int e = tid; e < 64 * 16; e += 256) s_Wc[e >> 4][e & 15] = Wc[e];

    // sinusoidal PE for all 8 windows (512 values, 2 per thread)
    for (int e = tid; e < NWL * 64; e += 256) {
        int w = e >> 6, p = e & 63;
        float t = ds[row * NWL + w];
        float v;
        if (p < 32) v = __sinf(t * __expf(-0.28782313662425575f * (float)p));
        else        v = __cosf(t * __expf(-0.28782313662425575f * (float)(p - 32)));
        s_pe[w][p] = v;
    }

    // ---- top[j] = qn @ Wtop[:,j] partials, tree-reduced ----
#pragma unroll
    for (int j = 0; j < 12; j++) s_part[tid][j]      = qn * w_delta[tid * 12 + j];
#pragma unroll
    for (int j = 0; j < 4;  j++) s_part[tid][12 + j] = qn * w_alpha[tid * 4 + j];
    __syncthreads();
    for (int s = 128; s > 0; s >>= 1) {
        if (tid < s) {
#pragma unroll
            for (int j = 0; j < 16; j++) s_part[tid][j] += s_part[tid + s][j];
        }
        __syncthreads();
    }
    if (tid < 16) s_top[tid] = s_part[0][tid];
    __syncthreads();

    // ---- per-window delta/logits: dl[w][j] = top[j] + pe_w @ Wc[:,j] + bc[j] ----
    if (tid < 128) {
        int w = tid >> 4, j = tid & 15;
        float acc = s_top[j] + bc[j];
#pragma unroll
        for (int p = 0; p < 64; p++) acc = fmaf(s_pe[w][p], s_Wc[p][j], acc);
        s_dl[w][j] = acc;
    }
    __syncthreads();

    // ---- softmax weights + tanh precompute ----
    if (tid < NWL) {
        float sp  = log1pf(expf(lam[0]));
        float pen = sp * fabsf(s_ds[tid]);
        float z0 = s_dl[tid][12] - pen, z1 = s_dl[tid][13] - pen;
        float z2 = s_dl[tid][14] - pen, z3 = s_dl[tid][15] - pen;
        float mx = fmaxf(fmaxf(z0, z1), fmaxf(z2, z3));
        float e0 = expf(z0 - mx), e1 = expf(z1 - mx), e2 = expf(z2 - mx), e3 = expf(z3 - mx);
        float inv = 1.f / (e0 + e1 + e2 + e3);
        s_wt[tid][0] = e0 * inv; s_wt[tid][1] = e1 * inv;
        s_wt[tid][2] = e2 * inv; s_wt[tid][3] = e3 * inv;
    }
    if (tid >= 32 && tid < 128) {
        int t2 = tid - 32;
        int w = t2 / 12, j = t2 % 12;
        s_tan[w][j] = tanhf(s_dl[w][j]);
    }
    __syncthreads();

    // ---- per-(w,m) sampling parameters (threads 0..31) ----
    if (tid < 32) {
        int w = tid >> 2, m = tid & 3;
        float cx = fminf(fmaxf(s_ref[0] + s_tan[w][m * 3 + 0], 0.f), 1.f);
        float cy = fminf(fmaxf(s_ref[1] + s_tan[w][m * 3 + 1], 0.f), 1.f);
        float dt = s_tan[w][m * 3 + 2];
        float target = (float)w + dt;
        float t0f = fminf(fmaxf(floorf(target), 0.f), (float)(NWL - 1));
        float t1f = fminf(t0f + 1.f, (float)(NWL - 1));
        float alpha = target - t0f;
        float px = cx * (float)NW - 0.5f, py = cy * (float)NH - 0.5f;
        float x0f = floorf(px), y0f = floorf(py);
        s_samp[tid][0] = __int_as_float(min(max((int)x0f, 0), NW - 1));
        s_samp[tid][1] = __int_as_float(min(max((int)x0f + 1, 0), NW - 1));
        s_samp[tid][2] = px - x0f;
        s_samp[tid][3] = __int_as_float(min(max((int)y0f, 0), NH - 1));
        s_samp[tid][4] = __int_as_float(min(max((int)y0f + 1, 0), NH - 1));
        s_samp[tid][5] = py - y0f;
        s_samp[tid][6] = __int_as_float((int)t0f);
        s_samp[tid][7] = __int_as_float((int)t1f);
        s_samp[tid][8] = alpha;
        s_samp[tid][9] = s_wt[w][m];
    }
    __syncthreads();

    // ---- emit 256 (offset, weight) pairs: sample s = tid>>3, corner c = tid&7
    {
        int s = tid >> 3, c = tid & 7;
        int   x  = __float_as_int(s_samp[s][(c & 1) ? 1 : 0]);
        float wxv = s_samp[s][2];
        float wxc = (c & 1) ? wxv : (1.f - wxv);
        int   y  = __float_as_int(s_samp[s][(c & 2) ? 4 : 3]);
        float wyv = s_samp[s][5];
        float wyc = (c & 2) ? wyv : (1.f - wyv);
        int   t  = __float_as_int(s_samp[s][(c & 4) ? 7 : 6]);
        float al = s_samp[s][8];
        float twc = (c & 4) ? al : (1.f - al);
        float wgt = s_samp[s][9];

        int cell = ((b * NWL + t) * NH + y) * NW + x;
        float wfin = wgt * twc * wyc * wxc;
        if (kmask[cell]) wfin = 0.f;
        PAIR[row * 256 + tid] = make_float2(__int_as_float(cell), wfin);
    }
}

// ---------------------------------------------------------------------------
// Gather kernel: one CTA per query; 256 threads = 64 channel-quads x 4
// pair-groups. Pure float4 weighted row-gathers, then 4-way smem reduction.
__global__ void __launch_bounds__(256) gather_kernel(
    const float4* __restrict__ feats4, const float2* __restrict__ PAIR,
    float4* __restrict__ AGG4)
{
    __shared__ float2 s_pair[256];
    __shared__ float4 s_red[4][64];
    int row = blockIdx.x;
    int tid = threadIdx.x;
    s_pair[tid] = PAIR[row * 256 + tid];
    __syncthreads();

    int cq = tid & 63;    // channel quad (channels 4*cq .. 4*cq+3)
    int g  = tid >> 6;    // pair group 0..3 (64 pairs each)

    float4 acc = make_float4(0.f, 0.f, 0.f, 0.f);
#pragma unroll 4
    for (int i = 0; i < 64; i++) {
        float2 pr = s_pair[g * 64 + i];
        int   off = __float_as_int(pr.x);
        float w   = pr.y;
        float4 v  = feats4[off * 64 + cq];
        acc.x = fmaf(w, v.x, acc.x);
        acc.y = fmaf(w, v.y, acc.y);
        acc.z = fmaf(w, v.z, acc.z);
        acc.w = fmaf(w, v.w, acc.w);
    }
    s_red[g][cq] = acc;
    __syncthreads();
    if (g == 0) {
        float4 a0 = s_red[0][cq], a1 = s_red[1][cq], a2 = s_red[2][cq], a3 = s_red[3][cq];
        float4 t;
        t.x = (a0.x + a1.x) + (a2.x + a3.x);
        t.y = (a0.y + a1.y) + (a2.y + a3.y);
        t.z = (a0.z + a1.z) + (a2.z + a3.z);
        t.w = (a0.w + a1.w) + (a2.w + a3.w);
        AGG4[row * 64 + cq] = t;
    }
}

// ---------------------------------------------------------------------------
// LN2: one warp per row, float4 loads, shuffle-only reduction
__global__ void __launch_bounds__(256) ln2_kernel(
    const float* __restrict__ out, const float* __restrict__ g,
    const float* __restrict__ bpar, float* __restrict__ Hbuf)
{
    int wid = threadIdx.x >> 5, lane = threadIdx.x & 31;
    int row = blockIdx.x * 8 + wid;
    const float4* o4 = (const float4*)out + row * 64;
    float4 v0 = o4[lane * 2], v1 = o4[lane * 2 + 1];
    float s = (v0.x + v0.y) + (v0.z + v0.w) + (v1.x + v1.y) + (v1.z + v1.w);
#pragma unroll
    for (int o = 16; o > 0; o >>= 1) s += __shfl_xor_sync(0xffffffffu, s, o);
    float mean = s * (1.f / 256.f);
    float d0x = v0.x - mean, d0y = v0.y - mean, d0z = v0.z - mean, d0w = v0.w - mean;
    float d1x = v1.x - mean, d1y = v1.y - mean, d1z = v1.z - mean, d1w = v1.w - mean;
    float sq = (d0x*d0x + d0y*d0y) + (d0z*d0z + d0w*d0w)
             + (d1x*d1x + d1y*d1y) + (d1z*d1z + d1w*d1w);
#pragma unroll
    for (int o = 16; o > 0; o >>= 1) sq += __shfl_xor_sync(0xffffffffu, sq, o);
    float inv = rsqrtf(sq * (1.f / 256.f) + 1e-5f);
    const float4* g4 = (const float4*)g;
    const float4* b4 = (const float4*)bpar;
    float4* H4 = (float4*)Hbuf + row * 64;
    float4 ga = g4[lane * 2], gb = g4[lane * 2 + 1];
    float4 ba = b4[lane * 2], bb = b4[lane * 2 + 1];
    float4 r0, r1;
    r0.x = d0x * inv * ga.x + ba.x; r0.y = d0y * inv * ga.y + ba.y;
    r0.z = d0z * inv * ga.z + ba.z; r0.w = d0w * inv * ga.w + ba.w;
    r1.x = d1x * inv * gb.x + bb.x; r1.y = d1y * inv * gb.y + bb.y;
    r1.z = d1z * inv * gb.z + bb.z; r1.w = d1w * inv * gb.w + bb.w;
    H4[lane * 2]     = r0;
    H4[lane * 2 + 1] = r1;
}

// ---------------------------------------------------------------------------
// TF32 tensor-core GEMM: C (=|+=) epi( A[M,K] @ W[K,N] + bias (+resid) )
// CTA tile 64x64 (4 warps, 2x2 of 32x32 warp tiles), BK=32, double-buffered.
#define AS_STRIDE 36
#define BS_STRIDE 72
template<bool GELU, bool ACC, bool RESID>
__global__ void __launch_bounds__(128) tgemm_k(
    const float* __restrict__ A, const float* __restrict__ W,
    const float* __restrict__ bias, const float* __restrict__ resid,
    float* __restrict__ C, int M, int N, int K)
{
    __shared__ unsigned As[2][64 * AS_STRIDE];   // [buf][m*36+k]
    __shared__ unsigned Bs[2][32 * BS_STRIDE];   // [buf][k*72+n]

    int tid  = threadIdx.x;
    int m0   = blockIdx.x * 64, n0 = blockIdx.y * 64;
    int warp = tid >> 5, lane = tid & 31;
    int wm   = (warp & 1) * 32, wn = (warp >> 1) * 32;
    int g    = lane >> 2, tig = lane & 3;

    float d[2][4][4];
#pragma unroll
    for (int mt = 0; mt < 2; mt++)
#pragma unroll
        for (int nt = 0; nt < 4; nt++)
#pragma unroll
            for (int e = 0; e < 4; e++) d[mt][nt][e] = 0.f;

    int nIter = K / 32;
    float4 pa[4];
    float4 pb[4];

    // prefetch tile 0
#pragma unroll
    for (int i = 0; i < 4; i++) {
        int e = tid + i * 128;
        int m = e >> 3, kq = e & 7;
        int gm = m0 + m;
        pa[i] = (gm < M) ? *(const float4*)(A + gm * K + kq * 4)
                         : make_float4(0.f, 0.f, 0.f, 0.f);
        int kk = e >> 4, nq = e & 15;
        pb[i] = *(const float4*)(W + kk * N + n0 + nq * 4);
    }
    // store tile 0 -> buf 0 (with tf32 RNA conversion)
#pragma unroll
    for (int i = 0; i < 4; i++) {
        int e = tid + i * 128;
        int m = e >> 3, kq = e & 7;
        *(uint4*)&As[0][m * AS_STRIDE + kq * 4] =
            make_uint4(f2tf32(pa[i].x), f2tf32(pa[i].y), f2tf32(pa[i].z), f2tf32(pa[i].w));
        int kk = e >> 4, nq = e & 15;
        *(uint4*)&Bs[0][kk * BS_STRIDE + nq * 4] =
            make_uint4(f2tf32(pb[i].x), f2tf32(pb[i].y), f2tf32(pb[i].z), f2tf32(pb[i].w));
    }
    __syncthreads();

    for (int it = 0; it < nIter; it++) {
        int cur = it & 1;
        if (it + 1 < nIter) {
            int k0 = (it + 1) * 32;
#pragma unroll
            for (int i = 0; i < 4; i++) {
                int e = tid + i * 128;
                int m = e >> 3, kq = e & 7;
                int gm = m0 + m;
                pa[i] = (gm < M) ? *(const float4*)(A + gm * K + k0 + kq * 4)
                                 : make_float4(0.f, 0.f, 0.f, 0.f);
                int kk = e >> 4, nq = e & 15;
                pb[i] = *(const float4*)(W + (k0 + kk) * N + n0 + nq * 4);
            }
        }

        const unsigned* Ac = &As[cur][0];
        const unsigned* Bc = &Bs[cur][0];
#pragma unroll
        for (int k8 = 0; k8 < 4; k8++) {
            int kb = k8 * 8;
            unsigned afrag[2][4];
            unsigned bfrag[4][2];
#pragma unroll
            for (int mt = 0; mt < 2; mt++) {
                int r = wm + mt * 16;
                afrag[mt][0] = Ac[(r + g)     * AS_STRIDE + kb + tig];
                afrag[mt][1] = Ac[(r + g + 8) * AS_STRIDE + kb + tig];
                afrag[mt][2] = Ac[(r + g)     * AS_STRIDE + kb + tig + 4];
                afrag[mt][3] = Ac[(r + g + 8) * AS_STRIDE + kb + tig + 4];
            }
#pragma unroll
            for (int nt = 0; nt < 4; nt++) {
                int c = wn + nt * 8 + g;
                bfrag[nt][0] = Bc[(kb + tig)     * BS_STRIDE + c];
                bfrag[nt][1] = Bc[(kb + tig + 4) * BS_STRIDE + c];
            }
#pragma unroll
            for (int mt = 0; mt < 2; mt++)
#pragma unroll
                for (int nt = 0; nt < 4; nt++)
                    asm volatile(
                        "mma.sync.aligned.m16n8k8.row.col.f32.tf32.tf32.f32 "
                        "{%0,%1,%2,%3},{%4,%5,%6,%7},{%8,%9},{%0,%1,%2,%3};"
                        : "+f"(d[mt][nt][0]), "+f"(d[mt][nt][1]),
                          "+f"(d[mt][nt][2]), "+f"(d[mt][nt][3])
                        : "r"(afrag[mt][0]), "r"(afrag[mt][1]),
                          "r"(afrag[mt][2]), "r"(afrag[mt][3]),
                          "r"(bfrag[nt][0]), "r"(bfrag[nt][1]));
        }

        if (it + 1 < nIter) {
            int nb = cur ^ 1;
#pragma unroll
            for (int i = 0; i < 4; i++) {
                int e = tid + i * 128;
                int m = e >> 3, kq = e & 7;
                *(uint4*)&As[nb][m * AS_STRIDE + kq * 4] =
                    make_uint4(f2tf32(pa[i].x), f2tf32(pa[i].y), f2tf32(pa[i].z), f2tf32(pa[i].w));
                int kk = e >> 4, nq = e & 15;
                *(uint4*)&Bs[nb][kk * BS_STRIDE + nq * 4] =
                    make_uint4(f2tf32(pb[i].x), f2tf32(pb[i].y), f2tf32(pb[i].z), f2tf32(pb[i].w));
            }
        }
        __syncthreads();
    }

    // epilogue: d0->(g,2t) d1->(g,2t+1) d2->(g+8,2t) d3->(g+8,2t+1)
#pragma unroll
    for (int mt = 0; mt < 2; mt++) {
#pragma unroll
        for (int nt = 0; nt < 4; nt++) {
            int c = n0 + wn + nt * 8 + 2 * tig;
            float b0 = bias[c], b1 = bias[c + 1];
#pragma unroll
            for (int h = 0; h < 2; h++) {
                int r = m0 + wm + mt * 16 + g + h * 8;
                if (r >= M) continue;
                float v0 = d[mt][nt][2 * h + 0] + b0;
                float v1 = d[mt][nt][2 * h + 1] + b1;
                if (RESID) {
                    v0 += resid[r * N + c];
                    v1 += resid[r * N + c + 1];
                }
                if (GELU) {
                    v0 = 0.5f * v0 * (1.f + erff(v0 * 0.70710678118654752f));
                    v1 = 0.5f * v1 * (1.f + erff(v1 * 0.70710678118654752f));
                }
                if (ACC) {
                    C[r * N + c]     += v0;
                    C[r * N + c + 1] += v1;
                } else {
                    *(float2*)(C + r * N + c) = make_float2(v0, v1);
                }
            }
        }
    }
}

// ---------------------------------------------------------------------------
extern "C" void kernel_launch(void* const* d_in, const int* in_sizes, int n_in,
                              void* d_out, int out_size)
{
    const float* q       = (const float*)d_in[0];
    const float* feats   = (const float*)d_in[1];
    const unsigned char* kmask = (const unsigned char*)d_in[2];
    const float* ds      = (const float*)d_in[3];
    const float* w_ref   = (const float*)d_in[4];
    const float* b_ref   = (const float*)d_in[5];
    const float* w_delta = (const float*)d_in[6];
    const float* b_delta = (const float*)d_in[7];
    const float* w_alpha = (const float*)d_in[8];
    const float* b_alpha = (const float*)d_in[9];
    const float* lam     = (const float*)d_in[10];
    const float* w_proj  = (const float*)d_in[11];
    const float* b_proj  = (const float*)d_in[12];
    const float* ln1g    = (const float*)d_in[13];
    const float* ln1b    = (const float*)d_in[14];
    const float* ln2g    = (const float*)d_in[15];
    const float* ln2b    = (const float*)d_in[16];
    const float* w_ffn1  = (const float*)d_in[17];
    const float* b_ffn1  = (const float*)d_in[18];
    const float* w_ffn2  = (const float*)d_in[19];
    const float* b_ffn2  = (const float*)d_in[20];
    const float* w_rel   = (const float*)d_in[21];
    const float* b_rel   = (const float*)d_in[22];
    float* out = (float*)d_out;

    float *pAGG, *pH, *pG, *pWc, *pbc;
    float2* pPAIR;
    cudaGetSymbolAddress((void**)&pAGG,  g_AGG);
    cudaGetSymbolAddress((void**)&pH,    g_H);
    cudaGetSymbolAddress((void**)&pG,    g_G);
    cudaGetSymbolAddress((void**)&pWc,   g_Wc);
    cudaGetSymbolAddress((void**)&pbc,   g_bc);
    cudaGetSymbolAddress((void**)&pPAIR, g_PAIR);

    // 1) fold w_rel into the delta/alpha projections
    precomp_kernel<<<65, 256>>>(w_rel, b_rel, w_delta, b_delta, w_alpha, b_alpha, pWc, pbc);

    // 2) per-query sampling parameters -> 256 (offset, weight) pairs per query
    param_kernel<<<NROW, 256>>>(q, kmask, ds, w_ref, b_ref,
                                w_delta, w_alpha, lam, ln1g, ln1b, pWc, pbc, pPAIR);

    // 3) weighted gather -> AGG[1200,256]
    gather_kernel<<<NROW, 256>>>((const float4*)feats, pPAIR, (float4*)pAGG);

    // 4) out = q + AGG @ w_proj + b_proj      (M=1200,N=256,K=256)
    tgemm_k<false, false, true>
        <<<dim3(19, 4), 128>>>(pAGG, w_proj, b_proj, q, out, NROW, ND, ND);

    // 5) H = LN2(out)
    ln2_kernel<<<NROW / 8, 256>>>(out, ln2g, ln2b, pH);

    // 6) G = gelu(H @ w_ffn1 + b_ffn1)        (M=1200,N=1024,K=256)
    tgemm_k<true, false, false>
        <<<dim3(19, 16), 128>>>(pH, w_ffn1, b_ffn1, nullptr, pG, NROW, 4 * ND, ND);

    // 7) out += G @ w_ffn2 + b_ffn2           (M=1200,N=256,K=1024)
    tgemm_k<false, true, false>
        <<<dim3(19, 4), 128>>>(pG, w_ffn2, b_ffn2, nullptr, out, NROW, ND, 4 * ND);
}

// round 5
// speedup vs baseline: 2.0462x; 1.2301x over previous
#include <cuda_runtime.h>
#include <cuda_bf16.h>
#include <math.h>

// Shapes (fixed for this problem)
#define NB    4
#define NQ    300
#define NROW  1200     // NB*NQ
#define NWL   8
#define NH    64
#define NW    64
#define ND    256
#define NM    4

// Scratch (device globals — no allocation allowed)
__device__ float  g_AGG[NROW * ND];        // aggregated sampled features
__device__ float  g_H  [NROW * ND];        // ln2(out)
__device__ float  g_G  [NROW * 4 * ND];    // gelu(H @ w_ffn1 + b1)
__device__ float  g_Wc [64 * 16];          // w_rel @ [w_delta_bot | w_alpha_bot]
__device__ float  g_bc [16];               // combined bias
__device__ float2 g_PAIR[NROW * 256];      // (cell offset as int bits, weight)

// ---------------------------------------------------------------------------
// block-wide sum over 256 threads (deterministic)
__device__ __forceinline__ float blockReduce256(float v, float* sred) {
#pragma unroll
    for (int o = 16; o > 0; o >>= 1) v += __shfl_xor_sync(0xffffffffu, v, o);
    int lane = threadIdx.x & 31, w = threadIdx.x >> 5;
    __syncthreads();               // protect sred reuse across calls
    if (lane == 0) sred[w] = v;
    __syncthreads();
    return sred[0] + sred[1] + sred[2] + sred[3] + sred[4] + sred[5] + sred[6] + sred[7];
}

// 16B async copy, zero-fill when !pred
__device__ __forceinline__ void cpa16(unsigned saddr, const void* gptr, bool pred) {
    asm volatile("cp.async.cg.shared.global [%0], [%1], 16, %2;"
                 :: "r"(saddr), "l"(gptr), "r"(pred ? 16 : 0));
}

// ---------------------------------------------------------------------------
// Precompute Wcomb[p][j] = sum_k w_rel[p,k] * Wbot[k][j]  (p<64) and
// bcomb[j] = b_delta/b_alpha[j] + sum_k b_rel[k] * Wbot[k][j]  (block 64)
__global__ void __launch_bounds__(256) precomp_kernel(
    const float* __restrict__ w_rel, const float* __restrict__ b_rel,
    const float* __restrict__ w_delta, const float* __restrict__ b_delta,
    const float* __restrict__ w_alpha, const float* __restrict__ b_alpha,
    float* __restrict__ Wc, float* __restrict__ bc)
{
    __shared__ float sp[256][17];
    int p = blockIdx.x;            // 0..63 -> Wcomb row, 64 -> bias row
    int tid = threadIdx.x;
    float a = (p < 64) ? w_rel[p * 256 + tid] : b_rel[tid];
#pragma unroll
    for (int j = 0; j < 12; j++) sp[tid][j] = a * w_delta[(256 + tid) * 12 + j];
#pragma unroll
    for (int j = 0; j < 4; j++)  sp[tid][12 + j] = a * w_alpha[(256 + tid) * 4 + j];
    __syncthreads();
    for (int s = 128; s > 0; s >>= 1) {
        if (tid < s) {
#pragma unroll
            for (int j = 0; j < 16; j++) sp[tid][j] += sp[tid + s][j];
        }
        __syncthreads();
    }
    if (tid < 16) {
        if (p < 64) Wc[p * 16 + tid] = sp[0][tid];
        else        bc[tid] = sp[0][tid] + ((tid < 12) ? b_delta[tid] : b_alpha[tid - 12]);
    }
}

// ---------------------------------------------------------------------------
// Parameter kernel: one CTA per (b,q) row. Produces 256 (offset, weight)
// pairs per query: 32 samples x 8 trilinear corners.
__global__ void __launch_bounds__(256) param_kernel(
    const float* __restrict__ q,
    const unsigned char* __restrict__ kmask, const float* __restrict__ ds,
    const float* __restrict__ w_ref, const float* __restrict__ b_ref,
    const float* __restrict__ w_delta, const float* __restrict__ w_alpha,
    const float* __restrict__ lam,
    const float* __restrict__ ln1g, const float* __restrict__ ln1b,
    const float* __restrict__ Wc, const float* __restrict__ bc,
    float2* __restrict__ PAIR)
{
    int row = blockIdx.x;                 // 0..1199
    int b   = row / NQ;
    int tid = threadIdx.x;

    __shared__ float s_red[8];
    __shared__ float s_ref[2];
    __shared__ float s_ds[NWL];
    __shared__ float s_pe[NWL][64];
    __shared__ float s_Wc[64][17];
    __shared__ float s_top[16];
    __shared__ float s_dl[NWL][16];
    __shared__ float s_wt[NWL][NM];
    __shared__ float s_tan[NWL][12];
    __shared__ float s_samp[32][10];
    __shared__ float s_part[256][17];

    // ---- LN1 ----
    float qv   = q[row * ND + tid];
    float mean = blockReduce256(qv, s_red) * (1.f / 256.f);
    float dd   = qv - mean;
    float var  = blockReduce256(dd * dd, s_red) * (1.f / 256.f);
    float qn   = dd * rsqrtf(var + 1e-5f) * ln1g[tid] + ln1b[tid];

    // ---- reference point: sigmoid(qn @ w_ref + b_ref) ----
    float r0 = blockReduce256(qn * w_ref[2 * tid + 0], s_red);
    float r1 = blockReduce256(qn * w_ref[2 * tid + 1], s_red);
    if (tid == 0) {
        s_ref[0] = 1.f / (1.f + expf(-(r0 + b_ref[0])));
        s_ref[1] = 1.f / (1.f + expf(-(r1 + b_ref[1])));
    }
    if (tid < NWL) s_ds[tid] = ds[row * NWL + tid];

    // stage Wcomb to smem (padded: conflict-free)
    for (int e = tid; e < 64 * 16; e += 256) s_Wc[e >> 4][e & 15] = Wc[e];

    // sinusoidal PE for all 8 windows (512 values, 2 per thread)
    for (int e = tid; e < NWL * 64; e += 256) {
        int w = e >> 6, p = e & 63;
        float t = ds[row * NWL + w];
        float v;
        if (p < 32) v = __sinf(t * __expf(-0.28782313662425575f * (float)p));
        else        v = __cosf(t * __expf(-0.28782313662425575f * (float)(p - 32)));
        s_pe[w][p] = v;
    }

    // ---- top[j] = qn @ Wtop[:,j] partials, tree-reduced ----
#pragma unroll
    for (int j = 0; j < 12; j++) s_part[tid][j]      = qn * w_delta[tid * 12 + j];
#pragma unroll
    for (int j = 0; j < 4;  j++) s_part[tid][12 + j] = qn * w_alpha[tid * 4 + j];
    __syncthreads();
    for (int s = 128; s > 0; s >>= 1) {
        if (tid < s) {
#pragma unroll
            for (int j = 0; j < 16; j++) s_part[tid][j] += s_part[tid + s][j];
        }
        __syncthreads();
    }
    if (tid < 16) s_top[tid] = s_part[0][tid];
    __syncthreads();

    // ---- per-window delta/logits: dl[w][j] = top[j] + pe_w @ Wc[:,j] + bc[j] ----
    if (tid < 128) {
        int w = tid >> 4, j = tid & 15;
        float acc = s_top[j] + bc[j];
#pragma unroll
        for (int p = 0; p < 64; p++) acc = fmaf(s_pe[w][p], s_Wc[p][j], acc);
        s_dl[w][j] = acc;
    }
    __syncthreads();

    // ---- softmax weights + tanh precompute ----
    if (tid < NWL) {
        float sp  = log1pf(expf(lam[0]));
        float pen = sp * fabsf(s_ds[tid]);
        float z0 = s_dl[tid][12] - pen, z1 = s_dl[tid][13] - pen;
        float z2 = s_dl[tid][14] - pen, z3 = s_dl[tid][15] - pen;
        float mx = fmaxf(fmaxf(z0, z1), fmaxf(z2, z3));
        float e0 = expf(z0 - mx), e1 = expf(z1 - mx), e2 = expf(z2 - mx), e3 = expf(z3 - mx);
        float inv = 1.f / (e0 + e1 + e2 + e3);
        s_wt[tid][0] = e0 * inv; s_wt[tid][1] = e1 * inv;
        s_wt[tid][2] = e2 * inv; s_wt[tid][3] = e3 * inv;
    }
    if (tid >= 32 && tid < 128) {
        int t2 = tid - 32;
        int w = t2 / 12, j = t2 % 12;
        s_tan[w][j] = tanhf(s_dl[w][j]);
    }
    __syncthreads();

    // ---- per-(w,m) sampling parameters (threads 0..31) ----
    if (tid < 32) {
        int w = tid >> 2, m = tid & 3;
        float cx = fminf(fmaxf(s_ref[0] + s_tan[w][m * 3 + 0], 0.f), 1.f);
        float cy = fminf(fmaxf(s_ref[1] + s_tan[w][m * 3 + 1], 0.f), 1.f);
        float dt = s_tan[w][m * 3 + 2];
        float target = (float)w + dt;
        float t0f = fminf(fmaxf(floorf(target), 0.f), (float)(NWL - 1));
        float t1f = fminf(t0f + 1.f, (float)(NWL - 1));
        float alpha = target - t0f;
        float px = cx * (float)NW - 0.5f, py = cy * (float)NH - 0.5f;
        float x0f = floorf(px), y0f = floorf(py);
        s_samp[tid][0] = __int_as_float(min(max((int)x0f, 0), NW - 1));
        s_samp[tid][1] = __int_as_float(min(max((int)x0f + 1, 0), NW - 1));
        s_samp[tid][2] = px - x0f;
        s_samp[tid][3] = __int_as_float(min(max((int)y0f, 0), NH - 1));
        s_samp[tid][4] = __int_as_float(min(max((int)y0f + 1, 0), NH - 1));
        s_samp[tid][5] = py - y0f;
        s_samp[tid][6] = __int_as_float((int)t0f);
        s_samp[tid][7] = __int_as_float((int)t1f);
        s_samp[tid][8] = alpha;
        s_samp[tid][9] = s_wt[w][m];
    }
    __syncthreads();

    // ---- emit 256 (offset, weight) pairs: sample s = tid>>3, corner c = tid&7
    {
        int s = tid >> 3, c = tid & 7;
        int   x  = __float_as_int(s_samp[s][(c & 1) ? 1 : 0]);
        float wxv = s_samp[s][2];
        float wxc = (c & 1) ? wxv : (1.f - wxv);
        int   y  = __float_as_int(s_samp[s][(c & 2) ? 4 : 3]);
        float wyv = s_samp[s][5];
        float wyc = (c & 2) ? wyv : (1.f - wyv);
        int   t  = __float_as_int(s_samp[s][(c & 4) ? 7 : 6]);
        float al = s_samp[s][8];
        float twc = (c & 4) ? al : (1.f - al);
        float wgt = s_samp[s][9];

        int cell = ((b * NWL + t) * NH + y) * NW + x;
        float wfin = wgt * twc * wyc * wxc;
        if (kmask[cell]) wfin = 0.f;
        PAIR[row * 256 + tid] = make_float2(__int_as_float(cell), wfin);
    }
}

// ---------------------------------------------------------------------------
// Gather kernel: one CTA per query; 256 threads = 64 channel-quads x 4
// pair-groups. Pure float4 weighted row-gathers, then 4-way smem reduction.
__global__ void __launch_bounds__(256) gather_kernel(
    const float4* __restrict__ feats4, const float2* __restrict__ PAIR,
    float4* __restrict__ AGG4)
{
    __shared__ float2 s_pair[256];
    __shared__ float4 s_red[4][64];
    int row = blockIdx.x;
    int tid = threadIdx.x;
    s_pair[tid] = PAIR[row * 256 + tid];
    __syncthreads();

    int cq = tid & 63;    // channel quad (channels 4*cq .. 4*cq+3)
    int g  = tid >> 6;    // pair group 0..3 (64 pairs each)

    float4 acc = make_float4(0.f, 0.f, 0.f, 0.f);
#pragma unroll 4
    for (int i = 0; i < 64; i++) {
        float2 pr = s_pair[g * 64 + i];
        int   off = __float_as_int(pr.x);
        float w   = pr.y;
        float4 v  = feats4[off * 64 + cq];
        acc.x = fmaf(w, v.x, acc.x);
        acc.y = fmaf(w, v.y, acc.y);
        acc.z = fmaf(w, v.z, acc.z);
        acc.w = fmaf(w, v.w, acc.w);
    }
    s_red[g][cq] = acc;
    __syncthreads();
    if (g == 0) {
        float4 a0 = s_red[0][cq], a1 = s_red[1][cq], a2 = s_red[2][cq], a3 = s_red[3][cq];
        float4 t;
        t.x = (a0.x + a1.x) + (a2.x + a3.x);
        t.y = (a0.y + a1.y) + (a2.y + a3.y);
        t.z = (a0.z + a1.z) + (a2.z + a3.z);
        t.w = (a0.w + a1.w) + (a2.w + a3.w);
        AGG4[row * 64 + cq] = t;
    }
}

// ---------------------------------------------------------------------------
// LN2: one warp per row, float4 loads, shuffle-only reduction
__global__ void __launch_bounds__(256) ln2_kernel(
    const float* __restrict__ out, const float* __restrict__ g,
    const float* __restrict__ bpar, float* __restrict__ Hbuf)
{
    int wid = threadIdx.x >> 5, lane = threadIdx.x & 31;
    int row = blockIdx.x * 8 + wid;
    const float4* o4 = (const float4*)out + row * 64;
    float4 v0 = o4[lane * 2], v1 = o4[lane * 2 + 1];
    float s = (v0.x + v0.y) + (v0.z + v0.w) + (v1.x + v1.y) + (v1.z + v1.w);
#pragma unroll
    for (int o = 16; o > 0; o >>= 1) s += __shfl_xor_sync(0xffffffffu, s, o);
    float mean = s * (1.f / 256.f);
    float d0x = v0.x - mean, d0y = v0.y - mean, d0z = v0.z - mean, d0w = v0.w - mean;
    float d1x = v1.x - mean, d1y = v1.y - mean, d1z = v1.z - mean, d1w = v1.w - mean;
    float sq = (d0x*d0x + d0y*d0y) + (d0z*d0z + d0w*d0w)
             + (d1x*d1x + d1y*d1y) + (d1z*d1z + d1w*d1w);
#pragma unroll
    for (int o = 16; o > 0; o >>= 1) sq += __shfl_xor_sync(0xffffffffu, sq, o);
    float inv = rsqrtf(sq * (1.f / 256.f) + 1e-5f);
    const float4* g4 = (const float4*)g;
    const float4* b4 = (const float4*)bpar;
    float4* H4 = (float4*)Hbuf + row * 64;
    float4 ga = g4[lane * 2], gb = g4[lane * 2 + 1];
    float4 ba = b4[lane * 2], bb = b4[lane * 2 + 1];
    float4 r0, r1;
    r0.x = d0x * inv * ga.x + ba.x; r0.y = d0y * inv * ga.y + ba.y;
    r0.z = d0z * inv * ga.z + ba.z; r0.w = d0w * inv * ga.w + ba.w;
    r1.x = d1x * inv * gb.x + bb.x; r1.y = d1y * inv * gb.y + bb.y;
    r1.z = d1z * inv * gb.z + bb.z; r1.w = d1w * inv * gb.w + bb.w;
    H4[lane * 2]     = r0;
    H4[lane * 2 + 1] = r1;
}

// ---------------------------------------------------------------------------
// TF32 tensor-core GEMM with cp.async 3-stage pipeline.
// CTA tile 32(M) x 64(N), 4 warps (warp tile 16x32), BK=32.
// C (=|+=) epi( A[M,K] @ W[K,N] + bias (+resid) )
#define AS_STRIDE 36
#define BS_STRIDE 72
#define A_TILE_W  (32 * AS_STRIDE)
#define B_TILE_W  (32 * BS_STRIDE)
template<bool GELU, bool ACC, bool RESID>
__global__ void __launch_bounds__(128) tgemm_k(
    const float* __restrict__ A, const float* __restrict__ W,
    const float* __restrict__ bias, const float* __restrict__ resid,
    float* __restrict__ C, int M, int N, int K)
{
    __shared__ float As[3 * A_TILE_W];   // [stage][m*36+k]
    __shared__ float Bs[3 * B_TILE_W];   // [stage][k*72+n]

    int tid  = threadIdx.x;
    int m0   = blockIdx.x * 32, n0 = blockIdx.y * 64;
    int warp = tid >> 5, lane = tid & 31;
    int wm   = (warp & 1) * 16, wn = (warp >> 1) * 32;
    int g    = lane >> 2, tig = lane & 3;

    unsigned sA = (unsigned)__cvta_generic_to_shared(As);
    unsigned sB = (unsigned)__cvta_generic_to_shared(Bs);

    // A-load coords: 2 chunks/thread (e = tid + i*128), m = e>>3, kq = e&7
    int amIdx[2], akIdx[2];
#pragma unroll
    for (int i = 0; i < 2; i++) { int e = tid + i * 128; amIdx[i] = e >> 3; akIdx[i] = e & 7; }
    // B-load coords: 4 chunks/thread, kk = e>>4, nq = e&15
    int bkIdx[4], bnIdx[4];
#pragma unroll
    for (int i = 0; i < 4; i++) { int e = tid + i * 128; bkIdx[i] = e >> 4; bnIdx[i] = e & 15; }

    float d[4][4];
#pragma unroll
    for (int nt = 0; nt < 4; nt++)
#pragma unroll
        for (int e = 0; e < 4; e++) d[nt][e] = 0.f;

    int nIter = K / 32;

    // ---- issue loads for a stage ----
    auto issue = [&](int stage, int k0) {
#pragma unroll
        for (int i = 0; i < 2; i++) {
            int m = amIdx[i], kq = akIdx[i];
            int gm = m0 + m;
            cpa16(sA + (stage * A_TILE_W + m * AS_STRIDE + kq * 4) * 4,
                  A + (long)gm * K + k0 + kq * 4, gm < M);
        }
#pragma unroll
        for (int i = 0; i < 4; i++) {
            int kk = bkIdx[i], nq = bnIdx[i];
            cpa16(sB + (stage * B_TILE_W + kk * BS_STRIDE + nq * 4) * 4,
                  W + (long)(k0 + kk) * N + n0 + nq * 4, true);
        }
    };

    // prologue: stages 0,1
    issue(0, 0);
    asm volatile("cp.async.commit_group;");
    issue(1, 32);
    asm volatile("cp.async.commit_group;");

    int cs = 0, ws = 2;
    for (int it = 0; it < nIter; it++) {
        asm volatile("cp.async.wait_group 1;");
        __syncthreads();

        const float* Ac = As + cs * A_TILE_W;
        const float* Bc = Bs + cs * B_TILE_W;
#pragma unroll
        for (int k8 = 0; k8 < 4; k8++) {
            int kb = k8 * 8;
            unsigned afrag[4];
            unsigned bfrag[4][2];
            afrag[0] = __float_as_uint(Ac[(wm + g)     * AS_STRIDE + kb + tig]);
            afrag[1] = __float_as_uint(Ac[(wm + g + 8) * AS_STRIDE + kb + tig]);
            afrag[2] = __float_as_uint(Ac[(wm + g)     * AS_STRIDE + kb + tig + 4]);
            afrag[3] = __float_as_uint(Ac[(wm + g + 8) * AS_STRIDE + kb + tig + 4]);
#pragma unroll
            for (int nt = 0; nt < 4; nt++) {
                int c = wn + nt * 8 + g;
                bfrag[nt][0] = __float_as_uint(Bc[(kb + tig)     * BS_STRIDE + c]);
                bfrag[nt][1] = __float_as_uint(Bc[(kb + tig + 4) * BS_STRIDE + c]);
            }
#pragma unroll
            for (int nt = 0; nt < 4; nt++)
                asm volatile(
                    "mma.sync.aligned.m16n8k8.row.col.f32.tf32.tf32.f32 "
                    "{%0,%1,%2,%3},{%4,%5,%6,%7},{%8,%9},{%0,%1,%2,%3};"
                    : "+f"(d[nt][0]), "+f"(d[nt][1]), "+f"(d[nt][2]), "+f"(d[nt][3])
                    : "r"(afrag[0]), "r"(afrag[1]), "r"(afrag[2]), "r"(afrag[3]),
                      "r"(bfrag[nt][0]), "r"(bfrag[nt][1]));
        }

        if (it + 2 < nIter) issue(ws, (it + 2) * 32);
        asm volatile("cp.async.commit_group;");

        cs = (cs == 2) ? 0 : cs + 1;
        ws = (ws == 2) ? 0 : ws + 1;
    }

    // epilogue: d0->(g,2t) d1->(g,2t+1) d2->(g+8,2t) d3->(g+8,2t+1)
#pragma unroll
    for (int nt = 0; nt < 4; nt++) {
        int c = n0 + wn + nt * 8 + 2 * tig;
        float b0 = bias[c], b1 = bias[c + 1];
#pragma unroll
        for (int h = 0; h < 2; h++) {
            int r = m0 + wm + g + h * 8;
            if (r >= M) continue;
            float v0 = d[nt][2 * h + 0] + b0;
            float v1 = d[nt][2 * h + 1] + b1;
            if (RESID) {
                v0 += resid[r * N + c];
                v1 += resid[r * N + c + 1];
            }
            if (GELU) {
                v0 = 0.5f * v0 * (1.f + erff(v0 * 0.70710678118654752f));
                v1 = 0.5f * v1 * (1.f + erff(v1 * 0.70710678118654752f));
            }
            if (ACC) {
                C[r * N + c]     += v0;
                C[r * N + c + 1] += v1;
            } else {
                *(float2*)(C + r * N + c) = make_float2(v0, v1);
            }
        }
    }
}

// ---------------------------------------------------------------------------
extern "C" void kernel_launch(void* const* d_in, const int* in_sizes, int n_in,
                              void* d_out, int out_size)
{
    const float* q       = (const float*)d_in[0];
    const float* feats   = (const float*)d_in[1];
    const unsigned char* kmask = (const unsigned char*)d_in[2];
    const float* ds      = (const float*)d_in[3];
    const float* w_ref   = (const float*)d_in[4];
    const float* b_ref   = (const float*)d_in[5];
    const float* w_delta = (const float*)d_in[6];
    const float* b_delta = (const float*)d_in[7];
    const float* w_alpha = (const float*)d_in[8];
    const float* b_alpha = (const float*)d_in[9];
    const float* lam     = (const float*)d_in[10];
    const float* w_proj  = (const float*)d_in[11];
    const float* b_proj  = (const float*)d_in[12];
    const float* ln1g    = (const float*)d_in[13];
    const float* ln1b    = (const float*)d_in[14];
    const float* ln2g    = (const float*)d_in[15];
    const float* ln2b    = (const float*)d_in[16];
    const float* w_ffn1  = (const float*)d_in[17];
    const float* b_ffn1  = (const float*)d_in[18];
    const float* w_ffn2  = (const float*)d_in[19];
    const float* b_ffn2  = (const float*)d_in[20];
    const float* w_rel   = (const float*)d_in[21];
    const float* b_rel   = (const float*)d_in[22];
    float* out = (float*)d_out;

    float *pAGG, *pH, *pG, *pWc, *pbc;
    float2* pPAIR;
    cudaGetSymbolAddress((void**)&pAGG,  g_AGG);
    cudaGetSymbolAddress((void**)&pH,    g_H);
    cudaGetSymbolAddress((void**)&pG,    g_G);
    cudaGetSymbolAddress((void**)&pWc,   g_Wc);
    cudaGetSymbolAddress((void**)&pbc,   g_bc);
    cudaGetSymbolAddress((void**)&pPAIR, g_PAIR);

    // 1) fold w_rel into the delta/alpha projections
    precomp_kernel<<<65, 256>>>(w_rel, b_rel, w_delta, b_delta, w_alpha, b_alpha, pWc, pbc);

    // 2) per-query sampling parameters -> 256 (offset, weight) pairs per query
    param_kernel<<<NROW, 256>>>(q, kmask, ds, w_ref, b_ref,
                                w_delta, w_alpha, lam, ln1g, ln1b, pWc, pbc, pPAIR);

    // 3) weighted gather -> AGG[1200,256]
    gather_kernel<<<NROW, 256>>>((const float4*)feats, pPAIR, (float4*)pAGG);

    // 4) out = q + AGG @ w_proj + b_proj      (M=1200,N=256,K=256)
    tgemm_k<false, false, true>
        <<<dim3(38, 4), 128>>>(pAGG, w_proj, b_proj, q, out, NROW, ND, ND);

    // 5) H = LN2(out)
    ln2_kernel<<<NROW / 8, 256>>>(out, ln2g, ln2b, pH);

    // 6) G = gelu(H @ w_ffn1 + b_ffn1)        (M=1200,N=1024,K=256)
    tgemm_k<true, false, false>
        <<<dim3(38, 16), 128>>>(pH, w_ffn1, b_ffn1, nullptr, pG, NROW, 4 * ND, ND);

    // 7) out += G @ w_ffn2 + b_ffn2           (M=1200,N=256,K=1024)
    tgemm_k<false, true, false>
        <<<dim3(38, 4), 128>>>(pG, w_ffn2, b_ffn2, nullptr, out, NROW, ND, 4 * ND);
}